// round 9
// baseline (speedup 1.0000x reference)
#include <cuda_runtime.h>

// 15x15 separable Gaussian, 8192x8192 f32, reflect pad, stride 1.
// Fused separable conv, software-pipelined to break phase lockstep:
//   loop over 4 sub-chunks of 5 rows:
//     phase1(k): vertical conv, scalar FFMA-imm, register sliding window -> vbuf
//     prefetch(k+1): issue next sub-chunk's LDGs (consumed after the barrier)
//     barrier
//     phase2(k): horizontal conv on the 20 fresh vbuf rows, 8-output runs,
//                FFMA-imm, row-pair interleaved conflict-free LDS.128
// Coefficients hardcoded (problem-fixed Gaussian sigma=3, 15 taps);
// rel_err ~2.4e-7 verified across rounds.

#define IMW 8192
#define IMH 8192
#define TX  112          // output tile width (128 vbuf cols incl. 8+8 halo)
#define TY  80           // output tile height (4 groups x 20 rows)
#define VSTRIDE 132      // floats; 528 B row stride, 528 % 128 == 16
#define NSX 74           // ceil(8192/112)
#define NSY 103          // ceil(8192/80)

static __device__ __forceinline__ int refl(int i) {
    i = (i < 0) ? -i : i;
    return (i >= IMW) ? (2 * IMW - 2 - i) : i;
}

__global__ __launch_bounds__(256, 3)
void gauss_sep_kernel(const float* __restrict__ img,
                      float* __restrict__ out) {
    // normalized 1-D Gaussian, sigma=3, 15 taps (fp32)
    const float KC[15] = {
        0.00884695f, 0.01821590f, 0.03356240f, 0.05533503f,
        0.08163801f, 0.10777792f, 0.12732457f, 0.13459834f,
        0.12732457f, 0.10777792f, 0.08163801f, 0.05533503f,
        0.03356240f, 0.01821590f, 0.00884695f };

    __shared__ __align__(16) float vbuf[TY * VSTRIDE];   // 42.24 KB

    const int tid = threadIdx.x;
    const int bx = blockIdx.x;
    const int by = blockIdx.y;

    // phase-1 persistent state
    const int pc = tid & 63;            // float2 column 0..63 (128 vbuf cols)
    const int g  = tid >> 6;            // y-group 0..3 (20 rows each)
    const int gxp = bx * TX - 8 + 2 * pc;
    const bool xok = (gxp >= 0) && (gxp + 1 < IMW);
    const int rx0 = refl(gxp);
    const int rx1 = refl(gxp + 1);
    const int gy0 = by * TY + 20 * g;

    const int X0  = bx * TX;
    const int gyb = by * TY;

    // warm-up window: input rows gy0-7 .. gy0+6
    float2 win[15];
    #pragma unroll
    for (int i = 0; i < 14; i++) {
        const int ry = refl(gy0 - 7 + i);
        const float* rp = img + ry * IMW;
        if (xok) {
            win[i] = *reinterpret_cast<const float2*>(rp + gxp);
        } else {
            win[i].x = rp[rx0]; win[i].y = rp[rx1];
        }
    }
    // prefetch sub-chunk 0's 5 new rows (gy0+7 .. gy0+11)
    float2 pf[5];
    #pragma unroll
    for (int j = 0; j < 5; j++) {
        const int ry = refl(gy0 + 7 + j);
        const float* rp = img + ry * IMW;
        if (xok) {
            pf[j] = *reinterpret_cast<const float2*>(rp + gxp);
        } else {
            pf[j].x = rp[rx0]; pf[j].y = rp[rx1];
        }
    }

    #pragma unroll
    for (int k = 0; k < 4; k++) {
        // ---- phase 1: 5 sliding steps, scalar FFMA-imm vertical conv ----
        #pragma unroll
        for (int j = 0; j < 5; j++) {
            const int s = 5 * k + j;
            win[(14 + s) % 15] = pf[j];

            float ax = KC[0] * win[s % 15].x;
            float ay = KC[0] * win[s % 15].y;
            #pragma unroll
            for (int i = 1; i < 15; i++) {
                const float2 wi = win[(s + i) % 15];
                ax = fmaf(KC[i], wi.x, ax);
                ay = fmaf(KC[i], wi.y, ay);
            }
            *reinterpret_cast<float2*>(&vbuf[(20 * g + s) * VSTRIDE + 2 * pc]) =
                make_float2(ax, ay);
        }

        // ---- prefetch next sub-chunk's rows (LDGs in flight across barrier) ----
        if (k < 3) {
            #pragma unroll
            for (int j = 0; j < 5; j++) {
                const int ry = refl(gy0 + 5 * (k + 1) + 7 + j);
                const float* rp = img + ry * IMW;
                if (xok) {
                    pf[j] = *reinterpret_cast<const float2*>(rp + gxp);
                } else {
                    pf[j].x = rp[rx0]; pf[j].y = rp[rx1];
                }
            }
        }

        __syncthreads();

        // ---- phase 2: horizontal conv on this sub-chunk's 20 vbuf rows ----
        // rows vr = 20*gg + 5k + j (gg=0..3, j=0..4); 20 rows x 14 runs = 280 tasks.
        // Row-pair interleave -> 8-lane LDS.128 phases hit 8 distinct 16B banks.
        #pragma unroll
        for (int tt = 0; tt < 2; tt++) {
            const int t = tid + 256 * tt;
            if (t < 280) {
                const int r2 = t / 28;              // 0..9
                const int u  = t - r2 * 28;
                const int rr = 2 * r2 + (u & 1);    // 0..19
                const int q  = u >> 1;              // run 0..13
                const int vr = 20 * (rr / 5) + 5 * k + (rr % 5);

                const float* vp = &vbuf[vr * VSTRIDE + q * 8];
                float w[24];
                #pragma unroll
                for (int j4 = 0; j4 < 6; j4++) {
                    const float4 f = *reinterpret_cast<const float4*>(vp + 4 * j4);
                    w[4 * j4]     = f.x;
                    w[4 * j4 + 1] = f.y;
                    w[4 * j4 + 2] = f.z;
                    w[4 * j4 + 3] = f.w;
                }

                float o[8];
                #pragma unroll
                for (int kk = 0; kk < 8; kk++) o[kk] = KC[0] * w[1 + kk];
                #pragma unroll
                for (int i = 1; i < 15; i++) {
                    #pragma unroll
                    for (int kk = 0; kk < 8; kk++)
                        o[kk] = fmaf(KC[i], w[1 + kk + i], o[kk]);
                }

                const int gy = gyb + vr;
                const int gx = X0 + 8 * q;
                if (gy < IMH && gx + 7 < IMW) {
                    float* op = out + gy * IMW + gx;
                    *reinterpret_cast<float4*>(op) =
                        make_float4(o[0], o[1], o[2], o[3]);
                    *reinterpret_cast<float4*>(op + 4) =
                        make_float4(o[4], o[5], o[6], o[7]);
                }
            }
        }
        // no trailing barrier: phase1(k+1) writes vbuf rows disjoint from
        // phase2(k) reads; the next iteration's barrier orders its readers.
    }
}

extern "C" void kernel_launch(void* const* d_in, const int* in_sizes, int n_in,
                              void* d_out, int out_size) {
    const float* img = (const float*)d_in[0];
    float* out = (float*)d_out;

    dim3 grid(NSX, NSY);
    gauss_sep_kernel<<<grid, 256>>>(img, out);
}